// round 2
// baseline (speedup 1.0000x reference)
#include <cuda_runtime.h>
#include <cuda_bf16.h>
#include <math.h>

// Problem constants
#define BB 8
#define NN 4096
#define DD 512
#define HH 8
#define RR 256
#define DEP 64
#define MM (BB*NN)        // 32768
#define NCHUNK 8          // split-K chunks for projection
#define ROWS_PER_BLK 512  // attention rows per block

// ---------------------------------------------------------------------------
// Scratch (static device globals: allocation-free per harness rules)
// ---------------------------------------------------------------------------
__device__ float g_q[MM*DD];
__device__ float g_k[MM*DD];
__device__ float g_v[MM*DD];
__device__ float g_attn[MM*DD];
__device__ float g_kproj[BB*HH*RR*DEP];
__device__ float g_vproj[BB*HH*RR*DEP];
__device__ float g_partial[2*NCHUNK*BB*HH*RR*DEP];

// ---------------------------------------------------------------------------
// SGEMM: C[M,512] = A[M,512] @ W[512,512] (+ bias). BM=BN=128, BK=8, TM=TN=8.
// ---------------------------------------------------------------------------
template<bool BIAS>
__global__ __launch_bounds__(256)
void sgemm512(const float* __restrict__ A, const float* __restrict__ W,
              const float* __restrict__ bias, float* __restrict__ C) {
    const int K = DD, Nc = DD;
    __shared__ float As[8][128];
    __shared__ float Bs[8][128];
    const int bx = blockIdx.x;       // col block (0..3)
    const int by = blockIdx.y;       // row block (0..255)
    const int tid = threadIdx.x;
    const int tcol = tid & 15;
    const int trow = tid >> 4;

    const int aRow  = tid >> 1;
    const int aCol4 = (tid & 1) * 4;
    const int bRow  = tid >> 5;
    const int bCol4 = (tid & 31) * 4;

    const float* Aptr = A + (size_t)by * 128 * K;
    const float* Wptr = W + bx * 128;

    float acc[8][8];
    #pragma unroll
    for (int i = 0; i < 8; i++)
        #pragma unroll
        for (int j = 0; j < 8; j++) acc[i][j] = 0.f;

    for (int k0 = 0; k0 < K; k0 += 8) {
        float4 av = *(const float4*)(Aptr + (size_t)aRow * K + k0 + aCol4);
        As[aCol4+0][aRow] = av.x;
        As[aCol4+1][aRow] = av.y;
        As[aCol4+2][aRow] = av.z;
        As[aCol4+3][aRow] = av.w;
        float4 wv = *(const float4*)(Wptr + (size_t)(k0 + bRow) * Nc + bCol4);
        *(float4*)&Bs[bRow][bCol4] = wv;
        __syncthreads();
        #pragma unroll
        for (int k = 0; k < 8; k++) {
            float ar[8], br[8];
            #pragma unroll
            for (int i = 0; i < 8; i++) ar[i] = As[k][trow*8 + i];
            #pragma unroll
            for (int j = 0; j < 8; j++) br[j] = Bs[k][tcol*8 + j];
            #pragma unroll
            for (int i = 0; i < 8; i++)
                #pragma unroll
                for (int j = 0; j < 8; j++) acc[i][j] += ar[i] * br[j];
        }
        __syncthreads();
    }

    float bv[8];
    #pragma unroll
    for (int j = 0; j < 8; j++) bv[j] = BIAS ? bias[bx*128 + tcol*8 + j] : 0.f;

    #pragma unroll
    for (int i = 0; i < 8; i++) {
        size_t row = (size_t)by*128 + trow*8 + i;
        float* crow = C + row * Nc + bx*128 + tcol*8;
        #pragma unroll
        for (int j = 0; j < 8; j++) crow[j] = acc[i][j] + bv[j];
    }
}

// ---------------------------------------------------------------------------
// Projection partials: partial[which][chunk][bh][r][d] =
//   sum_{n in chunk} P[h,n,r] * src[b,n,h*64+d]
// grid: (NCHUNK, B*H, 2), block 256 (thread = r)
// ---------------------------------------------------------------------------
__global__ __launch_bounds__(256)
void proj_partial(const float* __restrict__ ksrc, const float* __restrict__ vsrc,
                  const float* __restrict__ E, const float* __restrict__ F) {
    const int chunk = blockIdx.x;
    const int bh    = blockIdx.y;
    const int which = blockIdx.z;
    const int b = bh >> 3, h = bh & 7;
    const float* src = which ? vsrc : ksrc;
    const float* P   = which ? F : E;
    const int r = threadIdx.x;

    __shared__ float ksh[8][64];
    float acc[DEP];
    #pragma unroll
    for (int d = 0; d < DEP; d++) acc[d] = 0.f;

    const int n0 = chunk * (NN / NCHUNK);
    const int nlen = NN / NCHUNK;   // 512
    for (int nn = 0; nn < nlen; nn += 8) {
        __syncthreads();
        for (int t = threadIdx.x; t < 8*64; t += 256) {
            int rr = t >> 6, d = t & 63;
            ksh[rr][d] = src[((size_t)b*NN + n0 + nn + rr) * DD + h*DEP + d];
        }
        __syncthreads();
        #pragma unroll
        for (int rr = 0; rr < 8; rr++) {
            float e = P[((size_t)h*NN + n0 + nn + rr) * RR + r];
            #pragma unroll
            for (int d = 0; d < DEP; d++) acc[d] += e * ksh[rr][d];
        }
    }
    float* out = g_partial + ((((size_t)which*NCHUNK + chunk)*(BB*HH) + bh)*RR + r) * DEP;
    #pragma unroll
    for (int d = 0; d < DEP; d++) out[d] = acc[d];
}

// ---------------------------------------------------------------------------
// Reduce projection partials (deterministic — no atomics)
// ---------------------------------------------------------------------------
__global__ void proj_reduce() {
    const size_t per = (size_t)BB*HH*RR*DEP;   // 1,048,576
    size_t idx = (size_t)blockIdx.x * blockDim.x + threadIdx.x;
    int which = blockIdx.y;
    if (idx >= per) return;
    float s = 0.f;
    #pragma unroll
    for (int c = 0; c < NCHUNK; c++)
        s += g_partial[((size_t)which*NCHUNK + c) * per + idx];
    (which ? g_vproj : g_kproj)[idx] = s;
}

// ---------------------------------------------------------------------------
// Fused attention: per (b,h): scores = q @ kproj^T * 1/8, softmax over R,
// out = p @ vproj. Writes g_attn in concat (B,N,D) layout.
// grid: (NN/ROWS_PER_BLK, B*H), block 256 (8 warps). Dynamic smem.
// ---------------------------------------------------------------------------
__global__ __launch_bounds__(256)
void attn_kernel() {
    extern __shared__ float smem[];
    float* kp   = smem;                 // [256][65]
    float* vp   = smem + RR*65;         // [256][65]
    float* pbuf = vp + RR*65;           // [8][256]
    float* qall = pbuf + 8*RR;          // [8][64]

    const int bh = blockIdx.y;
    const int b = bh >> 3, h = bh & 7;

    const float* kps = g_kproj + (size_t)bh * RR * DEP;
    const float* vps = g_vproj + (size_t)bh * RR * DEP;
    for (int t = threadIdx.x; t < RR*DEP; t += blockDim.x) {
        int r = t >> 6, d = t & 63;
        kp[r*65 + d] = kps[t];
        vp[r*65 + d] = vps[t];
    }
    __syncthreads();

    const int warp = threadIdx.x >> 5;
    const int lane = threadIdx.x & 31;
    float* p   = pbuf + warp * RR;
    float* qsh = qall + warp * DEP;
    const float scale = 0.125f;  // 1/sqrt(64)
    const int nstart = blockIdx.x * ROWS_PER_BLK;

    for (int n = nstart + warp; n < nstart + ROWS_PER_BLK; n += 8) {
        const float* qrow = g_q + ((size_t)b*NN + n) * DD + h*DEP;
        qsh[lane]      = qrow[lane];
        qsh[lane + 32] = qrow[lane + 32];
        __syncwarp();

        float sc[8];
        #pragma unroll
        for (int i = 0; i < 8; i++) {
            const int r = lane + 32*i;
            float s = 0.f;
            #pragma unroll
            for (int d = 0; d < DEP; d++) s += qsh[d] * kp[r*65 + d];
            sc[i] = s * scale;
        }
        // softmax over 256 (8 per lane x 32 lanes)
        float m = sc[0];
        #pragma unroll
        for (int i = 1; i < 8; i++) m = fmaxf(m, sc[i]);
        #pragma unroll
        for (int off = 16; off > 0; off >>= 1)
            m = fmaxf(m, __shfl_xor_sync(0xFFFFFFFFu, m, off));
        float sum = 0.f;
        #pragma unroll
        for (int i = 0; i < 8; i++) { sc[i] = __expf(sc[i] - m); sum += sc[i]; }
        #pragma unroll
        for (int off = 16; off > 0; off >>= 1)
            sum += __shfl_xor_sync(0xFFFFFFFFu, sum, off);
        const float inv = 1.f / sum;
        #pragma unroll
        for (int i = 0; i < 8; i++) p[lane + 32*i] = sc[i] * inv;
        __syncwarp();

        // out: lane owns columns d = lane and d = lane+32
        float o0 = 0.f, o1 = 0.f;
        #pragma unroll
        for (int r = 0; r < RR; r++) {
            const float pr = p[r];
            o0 += pr * vp[r*65 + lane];
            o1 += pr * vp[r*65 + lane + 32];
        }
        float* orow = g_attn + ((size_t)b*NN + n) * DD + h*DEP;
        orow[lane]      = o0;
        orow[lane + 32] = o1;
        __syncwarp();
    }
}

// ---------------------------------------------------------------------------
// Launch
// ---------------------------------------------------------------------------
extern "C" void kernel_launch(void* const* d_in, const int* in_sizes, int n_in,
                              void* d_out, int out_size) {
    const float* x       = (const float*)d_in[0];
    const float* wq      = (const float*)d_in[1];
    const float* wk      = (const float*)d_in[2];
    const float* wv      = (const float*)d_in[3];
    const float* E       = (const float*)d_in[4];
    const float* F       = (const float*)d_in[5];
    const float* w_dense = (const float*)d_in[6];
    const float* b_dense = (const float*)d_in[7];
    float* out = (float*)d_out;

    float *gq, *gk, *gv, *gattn;
    cudaGetSymbolAddress((void**)&gq,    g_q);
    cudaGetSymbolAddress((void**)&gk,    g_k);
    cudaGetSymbolAddress((void**)&gv,    g_v);
    cudaGetSymbolAddress((void**)&gattn, g_attn);

    // 1. QKV projections
    dim3 ggrid(DD/128, MM/128);
    sgemm512<false><<<ggrid, 256>>>(x, wq, nullptr, gq);
    sgemm512<false><<<ggrid, 256>>>(x, wk, nullptr, gk);
    sgemm512<false><<<ggrid, 256>>>(x, wv, nullptr, gv);

    // 2. Low-rank projections of K and V (split-K + reduce, deterministic)
    proj_partial<<<dim3(NCHUNK, BB*HH, 2), 256>>>(gk, gv, E, F);
    proj_reduce<<<dim3((BB*HH*RR*DEP + 255)/256, 2), 256>>>();

    // 3. Fused attention
    const int smem_bytes = (RR*65*2 + 8*RR + 8*DEP) * sizeof(float);  // ~143 KB
    static bool attr_set = false;
    if (!attr_set) {
        cudaFuncSetAttribute(attn_kernel,
                             cudaFuncAttributeMaxDynamicSharedMemorySize, smem_bytes);
        attr_set = true;
    }
    attn_kernel<<<dim3(NN/ROWS_PER_BLK, BB*HH), 256, smem_bytes>>>();

    // 4. Final dense + bias -> d_out
    sgemm512<true><<<ggrid, 256>>>(gattn, w_dense, b_dense, out);
}

// round 7
// speedup vs baseline: 3.0835x; 3.0835x over previous
#include <cuda_runtime.h>
#include <cuda_bf16.h>
#include <cstdint>
#include <math.h>

// Problem constants
#define BB 8
#define NN 4096
#define DD 512
#define HH 8
#define RR 256
#define DEP 64
#define MM (BB*NN)        // 32768
#define NCHUNK 8

// ===========================================================================
// PTX helpers — baseline ISA only (NO tcgen05/TMEM: harness targets sm_103
// without the 'a' suffix, which rejects arch-accelerated features)
// ===========================================================================
__device__ __forceinline__ uint32_t smem_to_u32(const void* smem_ptr) {
    uint32_t addr;
    asm("{ .reg .u64 tmp; cvta.to.shared.u64 tmp, %1; cvt.u32.u64 %0, tmp; }"
        : "=r"(addr) : "l"(smem_ptr));
    return addr;
}
__device__ __forceinline__ void cp16(uint32_t s, const void* g) {
    asm volatile("cp.async.cg.shared.global [%0], [%1], 16;" :: "r"(s), "l"(g));
}
#define CP_COMMIT() asm volatile("cp.async.commit_group;" ::: "memory")
#define CP_WAIT(n)  asm volatile("cp.async.wait_group %0;" :: "n"(n) : "memory")

__device__ __forceinline__ void ldsm4(uint32_t& r0, uint32_t& r1, uint32_t& r2,
                                      uint32_t& r3, uint32_t a) {
    asm volatile("ldmatrix.sync.aligned.m8n8.x4.shared.b16 {%0,%1,%2,%3}, [%4];"
                 : "=r"(r0), "=r"(r1), "=r"(r2), "=r"(r3) : "r"(a));
}
__device__ __forceinline__ void mma16816(float* c, const uint32_t* a, const uint32_t* b) {
    asm volatile(
        "mma.sync.aligned.m16n8k16.row.col.f32.bf16.bf16.f32 "
        "{%0,%1,%2,%3}, {%4,%5,%6,%7}, {%8,%9}, {%0,%1,%2,%3};"
        : "+f"(c[0]), "+f"(c[1]), "+f"(c[2]), "+f"(c[3])
        : "r"(a[0]), "r"(a[1]), "r"(a[2]), "r"(a[3]), "r"(b[0]), "r"(b[1]));
}

// packed fp32x2 FMA (base-target sm_100+ PTX)
__device__ __forceinline__ unsigned long long ffma2(unsigned long long a,
                                                    unsigned long long b,
                                                    unsigned long long c) {
    unsigned long long d;
    asm("fma.rn.f32x2 %0, %1, %2, %3;" : "=l"(d) : "l"(a), "l"(b), "l"(c));
    return d;
}
__device__ __forceinline__ unsigned long long pack2(float x, float y) {
    unsigned long long r;
    asm("mov.b64 %0, {%1, %2};" : "=l"(r) : "f"(x), "f"(y));
    return r;
}
__device__ __forceinline__ float2 unpack2(unsigned long long v) {
    float2 f;
    asm("mov.b64 {%0, %1}, %2;" : "=f"(f.x), "=f"(f.y) : "l"(v));
    return f;
}

// ===========================================================================
// Scratch (static device globals)
// ===========================================================================
__device__ float g_q[MM*DD];
__device__ float g_k[MM*DD];
__device__ float g_v[MM*DD];
__device__ float g_kproj[BB*HH*RR*DEP];
__device__ float g_vproj[BB*HH*RR*DEP];
__device__ float g_partial[2*NCHUNK*BB*HH*RR*DEP];
__device__ __nv_bfloat16 g_xh[MM*DD];
__device__ __nv_bfloat16 g_xl[MM*DD];
__device__ __nv_bfloat16 g_ah[MM*DD];
__device__ __nv_bfloat16 g_al[MM*DD];
__device__ __nv_bfloat16 g_wth[4*DD*DD];
__device__ __nv_bfloat16 g_wtl[4*DD*DD];

// ===========================================================================
// Split fp32 -> bf16 hi + bf16 lo (8 floats/thread)
// ===========================================================================
__global__ __launch_bounds__(256)
void convert_split(const float* __restrict__ src, __nv_bfloat16* __restrict__ hi,
                   __nv_bfloat16* __restrict__ lo, int n8) {
    int i = blockIdx.x * 256 + threadIdx.x;
    if (i >= n8) return;
    float4 a = ((const float4*)src)[2*i];
    float4 b = ((const float4*)src)[2*i+1];
    float v[8] = {a.x, a.y, a.z, a.w, b.x, b.y, b.z, b.w};
    unsigned hw[4], lw[4];
    #pragma unroll
    for (int j = 0; j < 4; j++) {
        __nv_bfloat16 h0 = __float2bfloat16(v[2*j]);
        __nv_bfloat16 h1 = __float2bfloat16(v[2*j+1]);
        float l0 = v[2*j]   - __bfloat162float(h0);
        float l1 = v[2*j+1] - __bfloat162float(h1);
        __nv_bfloat16 lb0 = __float2bfloat16(l0);
        __nv_bfloat16 lb1 = __float2bfloat16(l1);
        hw[j] = (unsigned)__bfloat16_as_ushort(h0) | ((unsigned)__bfloat16_as_ushort(h1) << 16);
        lw[j] = (unsigned)__bfloat16_as_ushort(lb0) | ((unsigned)__bfloat16_as_ushort(lb1) << 16);
    }
    uint4 H; H.x = hw[0]; H.y = hw[1]; H.z = hw[2]; H.w = hw[3];
    uint4 L; L.x = lw[0]; L.y = lw[1]; L.z = lw[2]; L.w = lw[3];
    ((uint4*)hi)[i] = H;
    ((uint4*)lo)[i] = L;
}

// Transpose + split weight: Th/Tl[n*512+k] = split(W[k*512+n])
__global__ __launch_bounds__(256)
void wt_convert(const float* __restrict__ W, __nv_bfloat16* __restrict__ th,
                __nv_bfloat16* __restrict__ tl) {
    int idx = blockIdx.x * 256 + threadIdx.x;   // 0 .. 262143
    int n = idx >> 9, k = idx & 511;
    float w = W[(size_t)k * DD + n];
    __nv_bfloat16 hb = __float2bfloat16(w);
    th[idx] = hb;
    tl[idx] = __float2bfloat16(w - __bfloat162float(hb));
}

// ===========================================================================
// mma.sync GEMM: C[32768,512] = A @ W (split bf16, 3-term), optional bias.
// A hi/lo [M,512] K-major; B = Wt hi/lo [N=512,K=512] K-major (== col-major B).
// Block tile 128x128, BK=32, 8 warps (warp tile 64x32), cp.async double buffer.
// grid (4, 256), 256 threads.
// ===========================================================================
#define ASTR 40                    // bf16 elems per smem row (32 data + 8 pad)
#define BUF_BYTES (128*ASTR*2)     // 10240 B per operand buffer
#define STAGE_BYTES (4*BUF_BYTES)  // Ah,Al,Bh,Bl per stage
#define GEMM_SMEM (2*STAGE_BYTES)  // 81920 B

__global__ __launch_bounds__(256)
void gemm_mma(const __nv_bfloat16* __restrict__ Ah, const __nv_bfloat16* __restrict__ Al,
              const __nv_bfloat16* __restrict__ Bh, const __nv_bfloat16* __restrict__ Bl,
              const float* __restrict__ bias, float* __restrict__ C, int useBias) {
    extern __shared__ char sm[];
    const uint32_t sbase = smem_to_u32(sm);
    const int tid = threadIdx.x;
    const int m0 = blockIdx.y * 128;
    const int n0 = blockIdx.x * 128;
    const int w = tid >> 5, lane = tid & 31;
    const int wm = w & 1, wn = w >> 1;   // warp tile: rows wm*64, cols wn*32

    // per-thread load slots: 2 chunks of 16B per operand buffer
    const int c0r = tid >> 2,        c0q = tid & 3;
    const int c1r = (tid + 256) >> 2, c1q = (tid + 256) & 3;

    float acc[4][4][4];
    #pragma unroll
    for (int mt = 0; mt < 4; mt++)
        #pragma unroll
        for (int nt = 0; nt < 4; nt++)
            #pragma unroll
            for (int i = 0; i < 4; i++) acc[mt][nt][i] = 0.f;

    auto prefetch = [&](int stage, int k0) {
        uint32_t st = sbase + stage * STAGE_BYTES;
        uint32_t soA0 = st + c0r * (ASTR*2) + c0q * 16;
        uint32_t soA1 = st + c1r * (ASTR*2) + c1q * 16;
        size_t gA0 = (size_t)(m0 + c0r) * DD + k0 + c0q * 8;
        size_t gA1 = (size_t)(m0 + c1r) * DD + k0 + c1q * 8;
        size_t gB0 = (size_t)(n0 + c0r) * DD + k0 + c0q * 8;
        size_t gB1 = (size_t)(n0 + c1r) * DD + k0 + c1q * 8;
        cp16(soA0 + 0*BUF_BYTES, Ah + gA0);
        cp16(soA1 + 0*BUF_BYTES, Ah + gA1);
        cp16(soA0 + 1*BUF_BYTES, Al + gA0);
        cp16(soA1 + 1*BUF_BYTES, Al + gA1);
        cp16(soA0 + 2*BUF_BYTES, Bh + gB0);
        cp16(soA1 + 2*BUF_BYTES, Bh + gB1);
        cp16(soA0 + 3*BUF_BYTES, Bl + gB0);
        cp16(soA1 + 3*BUF_BYTES, Bl + gB1);
    };

    prefetch(0, 0);
    CP_COMMIT();

    const int arow = wm*64 + (lane & 15);
    const int acolo = (lane >> 4) * 8;
    const int bnrow = wn*32 + (lane & 7) + ((lane >> 4) & 1) * 8;
    const int bko   = ((lane >> 3) & 1) * 8;

    for (int it = 0; it < 16; ++it) {
        if (it + 1 < 16) {
            prefetch((it + 1) & 1, (it + 1) * 32);
            CP_COMMIT();
            CP_WAIT(1);
        } else {
            CP_WAIT(0);
        }
        __syncthreads();
        uint32_t st = sbase + (it & 1) * STAGE_BYTES;

        #pragma unroll
        for (int kk = 0; kk < 2; kk++) {
            uint32_t aH[4][4], aL[4][4];
            const int acol = kk * 16 + acolo;
            #pragma unroll
            for (int mt = 0; mt < 4; mt++) {
                uint32_t ad = st + (uint32_t)(arow + mt*16) * (ASTR*2) + acol * 2;
                ldsm4(aH[mt][0], aH[mt][1], aH[mt][2], aH[mt][3], ad);
                ldsm4(aL[mt][0], aL[mt][1], aL[mt][2], aL[mt][3], ad + BUF_BYTES);
            }
            uint32_t bH[4][2], bL[4][2];
            const int bk = kk * 16 + bko;
            #pragma unroll
            for (int np = 0; np < 2; np++) {
                uint32_t bd = st + 2*BUF_BYTES +
                              (uint32_t)(bnrow + np*16) * (ASTR*2) + bk * 2;
                uint32_t r0, r1, r2, r3;
                ldsm4(r0, r1, r2, r3, bd);
                bH[2*np][0] = r0; bH[2*np][1] = r1;
                bH[2*np+1][0] = r2; bH[2*np+1][1] = r3;
                ldsm4(r0, r1, r2, r3, bd + BUF_BYTES);
                bL[2*np][0] = r0; bL[2*np][1] = r1;
                bL[2*np+1][0] = r2; bL[2*np+1][1] = r3;
            }
            #pragma unroll
            for (int mt = 0; mt < 4; mt++)
                #pragma unroll
                for (int nt = 0; nt < 4; nt++) {
                    mma16816(acc[mt][nt], aH[mt], bH[nt]);
                    mma16816(acc[mt][nt], aH[mt], bL[nt]);
                    mma16816(acc[mt][nt], aL[mt], bH[nt]);
                }
        }
        __syncthreads();
    }

    // epilogue
    const int g = lane >> 2, t4 = lane & 3;
    #pragma unroll
    for (int mt = 0; mt < 4; mt++) {
        const int row0 = m0 + wm*64 + mt*16 + g;
        #pragma unroll
        for (int nt = 0; nt < 4; nt++) {
            const int col = n0 + wn*32 + nt*8 + 2*t4;
            float2 v0 = make_float2(acc[mt][nt][0], acc[mt][nt][1]);
            float2 v1 = make_float2(acc[mt][nt][2], acc[mt][nt][3]);
            if (useBias) {
                float b0 = bias[col], b1 = bias[col + 1];
                v0.x += b0; v0.y += b1;
                v1.x += b0; v1.y += b1;
            }
            *(float2*)(C + (size_t)row0 * DD + col)       = v0;
            *(float2*)(C + (size_t)(row0 + 8) * DD + col) = v1;
        }
    }
}

// ===========================================================================
// Projection partials (FFMA2): partial[which][chunk][bh][r][d]
// ===========================================================================
__global__ __launch_bounds__(256)
void proj_partial(const float* __restrict__ ksrc, const float* __restrict__ vsrc,
                  const float* __restrict__ E, const float* __restrict__ F) {
    const int chunk = blockIdx.x;
    const int bh    = blockIdx.y;
    const int which = blockIdx.z;
    const int b = bh >> 3, h = bh & 7;
    const float* src = which ? vsrc : ksrc;
    const float* P   = which ? F : E;
    const int r = threadIdx.x;

    __shared__ float ksh[8][64];
    unsigned long long acc2[32];
    #pragma unroll
    for (int j = 0; j < 32; j++) acc2[j] = 0ull;

    const int n0 = chunk * (NN / NCHUNK);
    for (int nn = 0; nn < NN / NCHUNK; nn += 8) {
        __syncthreads();
        if (threadIdx.x < 128) {
            int rr = threadIdx.x >> 4, d4 = threadIdx.x & 15;
            *(float4*)&ksh[rr][d4 * 4] =
                *(const float4*)(src + ((size_t)b * NN + n0 + nn + rr) * DD + h * DEP + d4 * 4);
        }
        __syncthreads();
        #pragma unroll
        for (int rr = 0; rr < 8; rr++) {
            float e = P[((size_t)h * NN + n0 + nn + rr) * RR + r];
            unsigned long long e2 = pack2(e, e);
            #pragma unroll
            for (int j = 0; j < 32; j++)
                acc2[j] = ffma2(e2, *(const unsigned long long*)&ksh[rr][2 * j], acc2[j]);
        }
    }
    float* out = g_partial + ((((size_t)which * NCHUNK + chunk) * (BB * HH) + bh) * RR + r) * DEP;
    #pragma unroll
    for (int j = 0; j < 32; j++) {
        float2 f = unpack2(acc2[j]);
        *(float2*)&out[2 * j] = f;
    }
}

__global__ void proj_reduce() {
    const size_t per = (size_t)BB * HH * RR * DEP;
    size_t idx = (size_t)blockIdx.x * blockDim.x + threadIdx.x;
    int which = blockIdx.y;
    if (idx >= per) return;
    float s = 0.f;
    #pragma unroll
    for (int c = 0; c < NCHUNK; c++)
        s += g_partial[((size_t)which * NCHUNK + c) * per + idx];
    (which ? g_vproj : g_kproj)[idx] = s;
}

// ===========================================================================
// Fused attention: 4-row blocking + FFMA2. Writes bf16 hi/lo concat layout.
// grid (8, 64), 256 threads, dyn smem ~173KB.
// ===========================================================================
#define KP_STR 68
#define VT_STR 258
__global__ __launch_bounds__(256)
void attn2(const float* __restrict__ gq, __nv_bfloat16* __restrict__ oh,
           __nv_bfloat16* __restrict__ ol) {
    extern __shared__ float smf[];
    float* kp  = smf;                       // [256][68]
    float* vpT = smf + RR * KP_STR;         // [64][258]
    float* pb0 = vpT + DEP * VT_STR;        // 8 * 1024
    float* qs0 = pb0 + 8 * 1024;            // 8 * 272

    const int bh = blockIdx.y;
    const int b = bh >> 3, h = bh & 7;
    const float* kps = g_kproj + (size_t)bh * RR * DEP;
    const float* vps = g_vproj + (size_t)bh * RR * DEP;
    for (int t = threadIdx.x; t < RR * DEP; t += 256) {
        int r = t >> 6, d = t & 63;
        kp[r * KP_STR + d] = kps[t];
        vpT[d * VT_STR + r] = vps[t];
    }
    __syncthreads();

    const int warp = threadIdx.x >> 5, lane = threadIdx.x & 31;
    float* pb = pb0 + warp * 1024;          // [4][256]
    float* qs = qs0 + warp * 272;           // [4][68]
    const int nstart = blockIdx.x * 512;

    for (int nb = nstart; nb < nstart + 512; nb += 32) {
        const int nw = nb + warp * 4;
        #pragma unroll
        for (int row = 0; row < 4; row++) {
            const float* qrow = gq + ((size_t)b * NN + nw + row) * DD + h * DEP;
            qs[row * KP_STR + lane]      = qrow[lane];
            qs[row * KP_STR + lane + 32] = qrow[lane + 32];
        }
        __syncwarp();

        unsigned long long acc2[4][8];
        #pragma unroll
        for (int row = 0; row < 4; row++)
            #pragma unroll
            for (int i = 0; i < 8; i++) acc2[row][i] = 0ull;

        #pragma unroll 4
        for (int d4 = 0; d4 < 16; d4++) {
            ulonglong2 qv[4];
            #pragma unroll
            for (int row = 0; row < 4; row++)
                qv[row] = *(const ulonglong2*)(qs + row * KP_STR + d4 * 4);
            #pragma unroll
            for (int i = 0; i < 8; i++) {
                ulonglong2 kv = *(const ulonglong2*)(kp + (lane + 32 * i) * KP_STR + d4 * 4);
                #pragma unroll
                for (int row = 0; row < 4; row++) {
                    acc2[row][i] = ffma2(qv[row].x, kv.x, acc2[row][i]);
                    acc2[row][i] = ffma2(qv[row].y, kv.y, acc2[row][i]);
                }
            }
        }

        #pragma unroll
        for (int row = 0; row < 4; row++) {
            float sc[8];
            #pragma unroll
            for (int i = 0; i < 8; i++) {
                float2 f = unpack2(acc2[row][i]);
                sc[i] = (f.x + f.y) * 0.125f;
            }
            float m = sc[0];
            #pragma unroll
            for (int i = 1; i < 8; i++) m = fmaxf(m, sc[i]);
            #pragma unroll
            for (int off = 16; off > 0; off >>= 1)
                m = fmaxf(m, __shfl_xor_sync(0xFFFFFFFFu, m, off));
            float sum = 0.f;
            #pragma unroll
            for (int i = 0; i < 8; i++) { sc[i] = __expf(sc[i] - m); sum += sc[i]; }
            #pragma unroll
            for (int off = 16; off > 0; off >>= 1)
                sum += __shfl_xor_sync(0xFFFFFFFFu, sum, off);
            const float inv = 1.f / sum;
            #pragma unroll
            for (int i = 0; i < 8; i++) pb[row * 256 + lane + 32 * i] = sc[i] * inv;
        }
        __syncwarp();

        unsigned long long o2[4][2];
        #pragma unroll
        for (int row = 0; row < 4; row++) { o2[row][0] = 0ull; o2[row][1] = 0ull; }
        #pragma unroll 8
        for (int r2 = 0; r2 < 128; r2++) {
            unsigned long long v0 = *(const unsigned long long*)&vpT[lane * VT_STR + 2 * r2];
            unsigned long long v1 = *(const unsigned long long*)&vpT[(lane + 32) * VT_STR + 2 * r2];
            #pragma unroll
            for (int row = 0; row < 4; row++) {
                unsigned long long pv = *(const unsigned long long*)&pb[row * 256 + 2 * r2];
                o2[row][0] = ffma2(pv, v0, o2[row][0]);
                o2[row][1] = ffma2(pv, v1, o2[row][1]);
            }
        }
        #pragma unroll
        for (int row = 0; row < 4; row++) {
            float2 f0 = unpack2(o2[row][0]);
            float2 f1 = unpack2(o2[row][1]);
            float v0 = f0.x + f0.y, v1 = f1.x + f1.y;
            size_t base = ((size_t)b * NN + nw + row) * DD + h * DEP;
            __nv_bfloat16 hb0 = __float2bfloat16(v0);
            oh[base + lane] = hb0;
            ol[base + lane] = __float2bfloat16(v0 - __bfloat162float(hb0));
            __nv_bfloat16 hb1 = __float2bfloat16(v1);
            oh[base + lane + 32] = hb1;
            ol[base + lane + 32] = __float2bfloat16(v1 - __bfloat162float(hb1));
        }
        __syncwarp();
    }
}

// ===========================================================================
// Launch
// ===========================================================================
extern "C" void kernel_launch(void* const* d_in, const int* in_sizes, int n_in,
                              void* d_out, int out_size) {
    const float* x       = (const float*)d_in[0];
    const float* wq      = (const float*)d_in[1];
    const float* wk      = (const float*)d_in[2];
    const float* wv      = (const float*)d_in[3];
    const float* E       = (const float*)d_in[4];
    const float* F       = (const float*)d_in[5];
    const float* w_dense = (const float*)d_in[6];
    const float* b_dense = (const float*)d_in[7];
    float* out = (float*)d_out;

    float *gq, *gk, *gv;
    __nv_bfloat16 *xh, *xl, *ah, *al, *wth, *wtl;
    cudaGetSymbolAddress((void**)&gq,  g_q);
    cudaGetSymbolAddress((void**)&gk,  g_k);
    cudaGetSymbolAddress((void**)&gv,  g_v);
    cudaGetSymbolAddress((void**)&xh,  g_xh);
    cudaGetSymbolAddress((void**)&xl,  g_xl);
    cudaGetSymbolAddress((void**)&ah,  g_ah);
    cudaGetSymbolAddress((void**)&al,  g_al);
    cudaGetSymbolAddress((void**)&wth, g_wth);
    cudaGetSymbolAddress((void**)&wtl, g_wtl);

    const int attn_smem = (RR*KP_STR + DEP*VT_STR + 8*1024 + 8*272) * (int)sizeof(float);
    static bool attr_set = false;
    if (!attr_set) {
        cudaFuncSetAttribute(gemm_mma, cudaFuncAttributeMaxDynamicSharedMemorySize, GEMM_SMEM);
        cudaFuncSetAttribute(attn2, cudaFuncAttributeMaxDynamicSharedMemorySize, attn_smem);
        attr_set = true;
    }

    // Input conversions
    convert_split<<<(MM*DD/8 + 255)/256, 256>>>(x, xh, xl, MM*DD/8);
    wt_convert<<<1024, 256>>>(wq,      wth + 0*DD*DD, wtl + 0*DD*DD);
    wt_convert<<<1024, 256>>>(wk,      wth + 1*DD*DD, wtl + 1*DD*DD);
    wt_convert<<<1024, 256>>>(wv,      wth + 2*DD*DD, wtl + 2*DD*DD);
    wt_convert<<<1024, 256>>>(w_dense, wth + 3*DD*DD, wtl + 3*DD*DD);

    // QKV projections (mma.sync tensor path)
    dim3 ggrid(DD/128, MM/128);
    gemm_mma<<<ggrid, 256, GEMM_SMEM>>>(xh, xl, wth + 0*DD*DD, wtl + 0*DD*DD, nullptr, gq, 0);
    gemm_mma<<<ggrid, 256, GEMM_SMEM>>>(xh, xl, wth + 1*DD*DD, wtl + 1*DD*DD, nullptr, gk, 0);
    gemm_mma<<<ggrid, 256, GEMM_SMEM>>>(xh, xl, wth + 2*DD*DD, wtl + 2*DD*DD, nullptr, gv, 0);

    // Low-rank projections of K and V
    proj_partial<<<dim3(NCHUNK, BB*HH, 2), 256>>>(gk, gv, E, F);
    proj_reduce<<<dim3((BB*HH*RR*DEP + 255)/256, 2), 256>>>();

    // Fused attention -> bf16 hi/lo concat layout
    attn2<<<dim3(NN/512, BB*HH), 256, attn_smem>>>(gq, ah, al);

    // Final dense + bias (mma.sync) -> d_out
    gemm_mma<<<ggrid, 256, GEMM_SMEM>>>(ah, al, wth + 3*DD*DD, wtl + 3*DD*DD, b_dense, out, 1);
}